// round 2
// baseline (speedup 1.0000x reference)
#include <cuda_runtime.h>

#define TPB 128   // threads per block
#define BPB 128   // batches per block (== TPB, one batch per thread)

// Scratch in device globals (no allocation allowed).
__device__ float g_part[65536];
__device__ unsigned int g_count = 0;

__device__ __forceinline__ float sigmoidf(float x) {
    return 1.0f / (1.0f + expf(-x));
}

__global__ __launch_bounds__(TPB) void yolo_loss_kernel(
    const float4* __restrict__ pred,   // (B,3,8) f32 -> 6 float4 / batch
    const float4* __restrict__ gtb,    // (B,8,4) f32 -> 8 float4 / batch
    const int4*  __restrict__ gtc,     // (B,8)   i32 -> 2 int4  / batch
    float* __restrict__ out,
    int B, int nblocks)
{
    // Padded strides 7 / 9 / 3 (coprime with 8) => conflict-free LDS.128 reads.
    __shared__ float4 s_pred[BPB * 7];
    __shared__ float4 s_gtb [BPB * 9];
    __shared__ int4   s_gtc [BPB * 3];
    __shared__ float  s_red [TPB];
    __shared__ double s_d   [TPB];
    __shared__ bool   s_last;

    const int tid  = threadIdx.x;
    const int base = blockIdx.x * BPB;      // first batch of this block

    // ---- stage: fully coalesced linear loads, scattered into padded smem ----
#pragma unroll
    for (int it = 0; it < 6; it++) {        // pred: 768 float4 per block
        int idx = it * TPB + tid;
        int b = idx / 6, j = idx % 6;
        float4 v = make_float4(0.f, 0.f, 0.f, 0.f);
        if (base + b < B) v = pred[(size_t)base * 6 + idx];
        s_pred[b * 7 + j] = v;
    }
#pragma unroll
    for (int it = 0; it < 8; it++) {        // gtb: 1024 float4 per block
        int idx = it * TPB + tid;
        int b = idx / 8, j = idx % 8;
        float4 v = make_float4(0.f, 0.f, 0.f, 0.f);
        if (base + b < B) v = gtb[(size_t)base * 8 + idx];
        s_gtb[b * 9 + j] = v;
    }
#pragma unroll
    for (int it = 0; it < 2; it++) {        // gtc: 256 int4 per block
        int idx = it * TPB + tid;
        int b = idx / 2, j = idx % 2;
        int4 v = make_int4(0, 0, 0, 0);
        if (base + b < B) v = gtc[(size_t)base * 2 + idx];
        s_gtc[b * 3 + j] = v;
    }
    __syncthreads();

    // ---- compute: one batch per thread, all operands from smem ----
    float local = 0.0f;
    if (base + tid < B) {
        int4 c0 = s_gtc[tid * 3 + 0];
        int4 c1 = s_gtc[tid * 3 + 1];
        int cls[8] = {c0.x, c0.y, c0.z, c0.w, c1.x, c1.y, c1.z, c1.w};

#pragma unroll
        for (int a = 0; a < 3; a++) {
            float4 pa = s_pred[tid * 7 + a * 2 + 0];  // x,y,w,h
            float4 pb = s_pred[tid * 7 + a * 2 + 1];  // conf,l0,l1,l2

            float px = sigmoidf(pa.x);
            float py = sigmoidf(pa.y);
            float pw = pa.z;
            float ph = pa.w;
            float pconf = sigmoidf(pb.x);
            float l0 = pb.y, l1 = pb.z, l2 = pb.w;

            float px1 = px - pw * 0.5f, px2 = px + pw * 0.5f;
            float py1 = py - ph * 0.5f, py2 = py + ph * 0.5f;
            float parea = (px2 - px1) * (py2 - py1);

            float best = -__int_as_float(0x7f800000);  // -inf
            float mbx = 0.f, mby = 0.f, mbw = 0.f, mbh = 0.f;
            int bcls = 0;
#pragma unroll
            for (int n = 0; n < 8; n++) {
                float4 g = s_gtb[tid * 9 + n];
                float gx1 = g.x - g.z * 0.5f;
                float gx2 = g.x + g.z * 0.5f;
                float gy1 = g.y - g.w * 0.5f;
                float gy2 = g.y + g.w * 0.5f;
                float garea = (gx2 - gx1) * (gy2 - gy1);

                float iw = fmaxf(fminf(px2, gx2) - fmaxf(px1, gx1), 0.0f);
                float ih = fmaxf(fminf(py2, gy2) - fmaxf(py1, gy1), 0.0f);
                float inter = iw * ih;
                float iou = inter / (parea + garea - inter + 1e-6f);
                if (iou > best) {
                    best = iou;
                    mbx = g.x; mby = g.y; mbw = g.z; mbh = g.w;
                    bcls = cls[n];
                }
            }

            bool matched = best > 0.5f;

            float logp   = fmaxf(logf(pconf),    -100.0f);
            float log1mp = fmaxf(log1pf(-pconf), -100.0f);
            local += matched ? -logp : -log1mp;

            if (matched) {
                float dx = px - mbx, dy = py - mby, dw = pw - mbw, dh = ph - mbh;
                float coord = dx * dx + dy * dy + dw * dw + dh * dh;

                float m = fmaxf(l0, fmaxf(l1, l2));
                float lse = m + logf(expf(l0 - m) + expf(l1 - m) + expf(l2 - m));
                float lc = (bcls == 0) ? l0 : (bcls == 1) ? l1 : l2;

                local += 5.0f * coord + (lse - lc);
            }
        }
    }

    // ---- block reduction (fp32) ----
    s_red[tid] = local;
    __syncthreads();
#pragma unroll
    for (int s = TPB / 2; s > 0; s >>= 1) {
        if (tid < s) s_red[tid] += s_red[tid + s];
        __syncthreads();
    }
    if (tid == 0) g_part[blockIdx.x] = s_red[0];

    // ---- last-block-done final reduce (double) ----
    __threadfence();
    if (tid == 0) {
        unsigned c = atomicAdd(&g_count, 1u);
        s_last = (c == (unsigned)(nblocks - 1));
    }
    __syncthreads();

    if (s_last) {
        double acc = 0.0;
        for (int i = tid; i < nblocks; i += TPB) acc += (double)g_part[i];
        s_d[tid] = acc;
        __syncthreads();
#pragma unroll
        for (int s = TPB / 2; s > 0; s >>= 1) {
            if (tid < s) s_d[tid] += s_d[tid + s];
            __syncthreads();
        }
        if (tid == 0) {
            out[0] = (float)(s_d[0] / (double)B);
            g_count = 0;   // reset for next (deterministic) call
        }
    }
}

extern "C" void kernel_launch(void* const* d_in, const int* in_sizes, int n_in,
                              void* d_out, int out_size) {
    const float4* pred = (const float4*)d_in[0];
    const float4* gtb  = (const float4*)d_in[1];
    const int4*   gtc  = (const int4*)d_in[2];
    float* out = (float*)d_out;

    int B = in_sizes[0] / 24;            // (B,3,8) floats
    int nblocks = (B + BPB - 1) / BPB;   // 8192 for B=1M (fits g_part)

    yolo_loss_kernel<<<nblocks, TPB>>>(pred, gtb, gtc, out, B, nblocks);
}

// round 4
// speedup vs baseline: 1.4580x; 1.4580x over previous
#include <cuda_runtime.h>

#define TPB 128
#define BPB 128

__device__ float g_part[65536];
__device__ unsigned int g_count = 0;

__global__ __launch_bounds__(TPB) void yolo_loss_kernel(
    const float4* __restrict__ pred,   // (B,3,8) f32 -> 6 float4 / batch
    const float4* __restrict__ gtb,    // (B,8,4) f32 -> 8 float4 / batch
    const int4*  __restrict__ gtc,     // (B,8)   i32 -> 2 int4  / batch
    float* __restrict__ out,
    int B, int nblocks)
{
    // Padded strides (7 / 9 / 9, coprime with bank count) => conflict-free reads.
    __shared__ float4 s_pred[BPB * 7];
    __shared__ float4 s_gtb [BPB * 9];
    __shared__ int    s_gtc [BPB * 9];
    __shared__ float  s_red [TPB];
    __shared__ double s_d   [TPB];
    __shared__ bool   s_last;

    const int tid  = threadIdx.x;
    const int base = blockIdx.x * BPB;

    // ---- stage: coalesced linear loads scattered into padded smem ----
#pragma unroll
    for (int it = 0; it < 6; it++) {            // pred: 768 float4 / block
        int idx = it * TPB + tid;
        int b = idx / 6, j = idx % 6;
        float4 v = make_float4(0.f, 0.f, 0.f, 0.f);
        if (base + b < B) v = pred[(size_t)base * 6 + idx];
        s_pred[b * 7 + j] = v;
    }
#pragma unroll
    for (int it = 0; it < 8; it++) {            // gtb: 1024 float4 / block
        int idx = it * TPB + tid;
        int b = idx / 8, j = idx % 8;
        float4 v = make_float4(0.f, 0.f, 0.f, 0.f);
        if (base + b < B) v = gtb[(size_t)base * 8 + idx];
        s_gtb[b * 9 + j] = v;
    }
#pragma unroll
    for (int it = 0; it < 2; it++) {            // gtc: 256 int4 / block
        int idx = it * TPB + tid;
        int b = idx / 2, j = idx % 2;
        int4 v = make_int4(0, 0, 0, 0);
        if (base + b < B) v = gtc[(size_t)base * 2 + idx];
        s_gtc[b * 9 + j * 4 + 0] = v.x;
        s_gtc[b * 9 + j * 4 + 1] = v.y;
        s_gtc[b * 9 + j * 4 + 2] = v.z;
        s_gtc[b * 9 + j * 4 + 3] = v.w;
    }
    __syncthreads();

    // ---- compute: one batch per thread ----
    float local = 0.0f;
    if (base + tid < B) {
#pragma unroll
        for (int a = 0; a < 3; a++) {
            float4 pa = s_pred[tid * 7 + a * 2 + 0];  // x, y, w, h
            float4 pb = s_pred[tid * 7 + a * 2 + 1];  // conf, l0, l1, l2

            float px = __fdividef(1.0f, 1.0f + __expf(-pa.x));
            float py = __fdividef(1.0f, 1.0f + __expf(-pa.y));
            float pw = pa.z, ph = pa.w;
            float tconf = pb.x;

            float px1 = px - pw * 0.5f, px2 = px + pw * 0.5f;
            float py1 = py - ph * 0.5f, py2 = py + ph * 0.5f;
            float parea = (px2 - px1) * (py2 - py1);

            // division-free argmax: iou = inter/union, union > 0
            float best_i = -1.0f, best_u = 1.0f;
            int bidx = 0;
#pragma unroll
            for (int n = 0; n < 8; n++) {
                float4 g = s_gtb[tid * 9 + n];
                float hw = g.z * 0.5f, hh = g.w * 0.5f;
                float gx1 = g.x - hw, gx2 = g.x + hw;
                float gy1 = g.y - hh, gy2 = g.y + hh;
                float garea = (gx2 - gx1) * (gy2 - gy1);

                float iw = fmaxf(fminf(px2, gx2) - fmaxf(px1, gx1), 0.0f);
                float ih = fmaxf(fminf(py2, gy2) - fmaxf(py1, gy1), 0.0f);
                float inter = iw * ih;
                float uni = parea + garea - inter + 1e-6f;

                if (inter * best_u > best_i * uni) {
                    best_i = inter; best_u = uni; bidx = n;
                }
            }

            bool matched = (best_i + best_i) > best_u;   // best_iou > 0.5

            // conf BCE via shared softplus:
            //   matched:  -log(sigmoid(t))   = max(-t,0) + log1p(e^{-|t|})
            //   else:     -log(1-sigmoid(t)) = max( t,0) + log1p(e^{-|t|})
            float eC = __expf(-fabsf(tconf));
            float lg = __logf(1.0f + eC);
            float conf = (matched ? fmaxf(-tconf, 0.0f) : fmaxf(tconf, 0.0f)) + lg;
            local += fminf(conf, 100.0f);

            if (matched) {
                float4 g = s_gtb[tid * 9 + bidx];
                int cls  = s_gtc[tid * 9 + bidx];

                float dx = px - g.x, dy = py - g.y;
                float dw = pw - g.z, dh = ph - g.w;
                float coord = dx * dx + dy * dy + dw * dw + dh * dh;

                float l0 = pb.y, l1 = pb.z, l2 = pb.w;
                float m = fmaxf(l0, fmaxf(l1, l2));
                float lse = m + __logf(__expf(l0 - m) + __expf(l1 - m) + __expf(l2 - m));
                float lc = (cls == 0) ? l0 : (cls == 1) ? l1 : l2;

                local += 5.0f * coord + (lse - lc);
            }
        }
    }

    // ---- block reduction (fp32) ----
    s_red[tid] = local;
    __syncthreads();
#pragma unroll
    for (int s = TPB / 2; s > 0; s >>= 1) {
        if (tid < s) s_red[tid] += s_red[tid + s];
        __syncthreads();
    }
    if (tid == 0) g_part[blockIdx.x] = s_red[0];

    // ---- last-block-done final reduce (double) ----
    __threadfence();
    if (tid == 0) {
        unsigned c = atomicAdd(&g_count, 1u);
        s_last = (c == (unsigned)(nblocks - 1));
    }
    __syncthreads();

    if (s_last) {
        double acc = 0.0;
        for (int i = tid; i < nblocks; i += TPB) acc += (double)g_part[i];
        s_d[tid] = acc;
        __syncthreads();
#pragma unroll
        for (int s = TPB / 2; s > 0; s >>= 1) {
            if (tid < s) s_d[tid] += s_d[tid + s];
            __syncthreads();
        }
        if (tid == 0) {
            out[0] = (float)(s_d[0] / (double)B);
            g_count = 0;
        }
    }
}

extern "C" void kernel_launch(void* const* d_in, const int* in_sizes, int n_in,
                              void* d_out, int out_size) {
    const float4* pred = (const float4*)d_in[0];
    const float4* gtb  = (const float4*)d_in[1];
    const int4*   gtc  = (const int4*)d_in[2];
    float* out = (float*)d_out;

    int B = in_sizes[0] / 24;
    int nblocks = (B + BPB - 1) / BPB;

    yolo_loss_kernel<<<nblocks, TPB>>>(pred, gtb, gtc, out, B, nblocks);
}

// round 5
// speedup vs baseline: 2.0407x; 1.3997x over previous
#include <cuda_runtime.h>

#define TPB 128
#define BPB 128

__device__ float g_part[65536];
__device__ unsigned int g_count = 0;

__global__ __launch_bounds__(TPB, 6) void yolo_loss_kernel(
    const float4* __restrict__ pred,   // (B,3,8) f32 -> 6 float4 / batch
    const float4* __restrict__ gtb,    // (B,8,4) f32 -> 8 float4 / batch
    const int*   __restrict__ gtc,     // (B,8)   i32
    float* __restrict__ out,
    int B, int nblocks)
{
    // padded strides 7 / 9 -> conflict-free LDS.128 (8-lane phases)
    __shared__ float4 s_pred[BPB * 7];           // 14336 B
    __shared__ float4 s_gtb [BPB * 9];           // 18432 B: (gx1|cls, gy1, gx2, gy2)
    __shared__ float  s_red [TPB / 32];
    __shared__ double s_d   [TPB / 32];
    __shared__ bool   s_last;

    const int tid  = threadIdx.x;
    const int lane = tid & 31;
    const int warp = tid >> 5;
    const int base = blockIdx.x * BPB;

    // ---- stage pred: coalesced, scattered into padded smem ----
#pragma unroll
    for (int it = 0; it < 6; it++) {
        int idx = it * TPB + tid;
        int b = idx / 6, j = idx % 6;
        float4 v = make_float4(0.f, 0.f, 0.f, 0.f);
        if (base + b < B) v = pred[(size_t)base * 6 + idx];
        s_pred[b * 7 + j] = v;
    }

    // ---- stage gt boxes: transform to corners + pack class into gx1 mantissa ----
#pragma unroll
    for (int it = 0; it < 8; it++) {
        int idx = it * TPB + tid;               // (b,n) pair; gtc index == idx too
        int b = idx / 8, n = idx % 8;
        float4 g = make_float4(0.f, 0.f, 0.f, 0.f);
        int cls = 0;
        if (base + b < B) {
            g   = gtb[(size_t)base * 8 + idx];
            cls = gtc[(size_t)base * 8 + idx];
        }
        float hw = g.z * 0.5f, hh = g.w * 0.5f;
        float gx1 = g.x - hw, gx2 = g.x + hw;
        float gy1 = g.y - hh, gy2 = g.y + hh;
        gx1 = __int_as_float((__float_as_int(gx1) & ~3) | (cls & 3));
        s_gtb[b * 9 + n] = make_float4(gx1, gy1, gx2, gy2);
    }
    __syncthreads();

    // ---- compute: one batch per thread ----
    float local = 0.0f;
    if (base + tid < B) {
        const float4* myg = &s_gtb[tid * 9];
        const float4* myp = &s_pred[tid * 7];

#pragma unroll 1
        for (int a = 0; a < 3; a++) {
            float4 pa = myp[a * 2 + 0];          // x, y, w, h
            float4 pb = myp[a * 2 + 1];          // conf, l0, l1, l2

            float px = __fdividef(1.0f, 1.0f + __expf(-pa.x));
            float py = __fdividef(1.0f, 1.0f + __expf(-pa.y));
            float pw = pa.z, ph = pa.w;

            float px1 = px - pw * 0.5f, px2 = px + pw * 0.5f;
            float py1 = py - ph * 0.5f, py2 = py + ph * 0.5f;
            float pbase = (px2 - px1) * (py2 - py1) + 1e-6f;   // parea + eps

            // argmax via monotonic int key: iou mantissa low 3 bits carry (7-n)
            int best = 0x80000000;
#pragma unroll
            for (int n = 0; n < 8; n++) {
                float4 g = myg[n];
                float garea = (g.z - g.x) * (g.w - g.y);
                float iw = fmaxf(fminf(px2, g.z) - fmaxf(px1, g.x), 0.0f);
                float ih = fmaxf(fminf(py2, g.w) - fmaxf(py1, g.y), 0.0f);
                float inter = iw * ih;
                float uni = pbase + garea - inter;
                float iou = __fdividef(inter, uni);
                int key = (__float_as_int(iou) & ~7) | (7 - n);
                best = max(best, key);
            }

            float biou = __int_as_float(best & ~7);
            bool matched = biou > 0.5f;

            // conf BCE via softplus (shared exp/log between both branches)
            float t = pb.x;
            float lg = __logf(1.0f + __expf(-fabsf(t)));
            float conf = (matched ? fmaxf(-t, 0.0f) : fmaxf(t, 0.0f)) + lg;
            local += fminf(conf, 100.0f);

            if (matched) {
                int bidx = 7 - (best & 7);
                float4 c = myg[bidx];
                int cls = __float_as_int(c.x) & 3;
                float gw = c.z - c.x, gh = c.w - c.y;
                float gx = (c.x + c.z) * 0.5f, gy = (c.y + c.w) * 0.5f;

                float dx = px - gx, dy = py - gy, dw = pw - gw, dh = ph - gh;
                float coord = dx * dx + dy * dy + dw * dw + dh * dh;

                float l0 = pb.y, l1 = pb.z, l2 = pb.w;
                float m = fmaxf(l0, fmaxf(l1, l2));
                float lse = m + __logf(__expf(l0 - m) + __expf(l1 - m) + __expf(l2 - m));
                float lc = (cls == 0) ? l0 : (cls == 1) ? l1 : l2;

                local += 5.0f * coord + (lse - lc);
            }
        }
    }

    // ---- warp-shuffle block reduction (fp32) ----
    float v = local;
#pragma unroll
    for (int o = 16; o > 0; o >>= 1) v += __shfl_down_sync(0xffffffffu, v, o);
    if (lane == 0) s_red[warp] = v;
    __syncthreads();
    if (warp == 0) {
        float w = (lane < TPB / 32) ? s_red[lane] : 0.0f;
#pragma unroll
        for (int o = 2; o > 0; o >>= 1) w += __shfl_down_sync(0xffffffffu, w, o);
        if (lane == 0) g_part[blockIdx.x] = w;
    }

    // ---- last-block-done final reduce ----
    __threadfence();
    if (tid == 0) {
        unsigned c = atomicAdd(&g_count, 1u);
        s_last = (c == (unsigned)(nblocks - 1));
    }
    __syncthreads();

    if (s_last) {
        float accf = 0.0f;
        for (int i = tid; i < nblocks; i += TPB) accf += g_part[i];
        double acc = (double)accf;
#pragma unroll
        for (int o = 16; o > 0; o >>= 1) acc += __shfl_down_sync(0xffffffffu, acc, o);
        if (lane == 0) s_d[warp] = acc;
        __syncthreads();
        if (warp == 0) {
            double w = (lane < TPB / 32) ? s_d[lane] : 0.0;
#pragma unroll
            for (int o = 2; o > 0; o >>= 1) w += __shfl_down_sync(0xffffffffu, w, o);
            if (lane == 0) {
                out[0] = (float)(w / (double)B);
                g_count = 0;
            }
        }
    }
}

extern "C" void kernel_launch(void* const* d_in, const int* in_sizes, int n_in,
                              void* d_out, int out_size) {
    const float4* pred = (const float4*)d_in[0];
    const float4* gtb  = (const float4*)d_in[1];
    const int*    gtc  = (const int*)d_in[2];
    float* out = (float*)d_out;

    int B = in_sizes[0] / 24;
    int nblocks = (B + BPB - 1) / BPB;

    yolo_loss_kernel<<<nblocks, TPB>>>(pred, gtb, gtc, out, B, nblocks);
}

// round 6
// speedup vs baseline: 2.0643x; 1.0116x over previous
#include <cuda_runtime.h>

#define TPB 128
#define BPB 128

__device__ float g_part[65536];
__device__ unsigned int g_count = 0;

template <bool FULL>
__global__ __launch_bounds__(TPB, 8) void yolo_loss_kernel(
    const float4* __restrict__ pred,   // (B,3,8) f32 -> 6 float4 / batch
    const float4* __restrict__ gtb,    // (B,8,4) f32 -> 8 float4 / batch
    const int*   __restrict__ gtc,     // (B,8)   i32
    float* __restrict__ out,
    int B, int nblocks)
{
    // s_p: [0..383]  = pa (x,y,w,h) per (b, anchor), stride 3 per batch
    //      [384..767]= pb (conf,l0,l1,l2),           stride 3 per batch
    // 48B batch stride -> 8-lane phase offsets all distinct mod 128: conflict-free.
    __shared__ float4 s_p  [2 * BPB * 3];      // 12288 B
    // s_gtb: stride 8 with XOR swizzle slot = n ^ (b&7): conflict-free R/W.
    __shared__ float4 s_gtb[BPB * 8];          // 16384 B  (total 28672 B)
    __shared__ bool   s_last;

    const int tid  = threadIdx.x;
    const int lane = tid & 31;
    const int warp = tid >> 5;
    const int base = blockIdx.x * BPB;
    const int sw   = tid & 7;

    // ---- stage pred: coalesced loads, scattered into split smem ----
    {
        int b = tid / 6, j = tid - b * 6;      // incremental (b, j) walk
#pragma unroll
        for (int it = 0; it < 6; it++) {
            float4 v;
            if (FULL || base + b < B) v = pred[(size_t)base * 6 + it * TPB + tid];
            else v = make_float4(0.f, 0.f, 0.f, 0.f);
            s_p[(j & 1) * (BPB * 3) + b * 3 + (j >> 1)] = v;
            b += 21; j += 2;
            if (j >= 6) { j -= 6; b += 1; }
        }
    }

    // ---- stage gt boxes: center->corner transform + class packed in gx1 lsbs ----
#pragma unroll
    for (int it = 0; it < 8; it++) {
        int idx = it * TPB + tid;
        int b = idx >> 3, n = idx & 7;
        float4 g;
        int cls = 0;
        if (FULL || base + b < B) {
            g   = gtb[(size_t)base * 8 + idx];
            cls = gtc[(size_t)base * 8 + idx];
        } else {
            g = make_float4(0.f, 0.f, 0.f, 0.f);
        }
        float hw = g.z * 0.5f, hh = g.w * 0.5f;
        float gx1 = g.x - hw, gx2 = g.x + hw;
        float gy1 = g.y - hh, gy2 = g.y + hh;
        gx1 = __int_as_float((__float_as_int(gx1) & ~3) | (cls & 3));
        s_gtb[(b << 3) | (n ^ (b & 7))] = make_float4(gx1, gy1, gx2, gy2);
    }
    __syncthreads();

    // ---- compute: one batch per thread ----
    float local = 0.0f;
    if (FULL || base + tid < B) {
#pragma unroll 1
        for (int a = 0; a < 3; a++) {
            float4 pa = s_p[tid * 3 + a];                 // x, y, w, h
            float4 pb = s_p[BPB * 3 + tid * 3 + a];       // conf, l0, l1, l2

            float px = __fdividef(1.0f, 1.0f + __expf(-pa.x));
            float py = __fdividef(1.0f, 1.0f + __expf(-pa.y));
            float pw = pa.z, ph = pa.w;

            float px1 = px - pw * 0.5f, px2 = px + pw * 0.5f;
            float py1 = py - ph * 0.5f, py2 = py + ph * 0.5f;
            float pbase = (px2 - px1) * (py2 - py1) + 1e-6f;

            // argmax via monotonic int key; low 3 bits carry (7-n) tiebreak
            int best = (int)0x80000000;
#pragma unroll
            for (int n = 0; n < 8; n++) {
                float4 g = s_gtb[(tid << 3) | (n ^ sw)];
                float garea = (g.z - g.x) * (g.w - g.y);
                float iw = fmaxf(fminf(px2, g.z) - fmaxf(px1, g.x), 0.0f);
                float ih = fmaxf(fminf(py2, g.w) - fmaxf(py1, g.y), 0.0f);
                float inter = iw * ih;
                float uni = pbase + garea - inter;
                float iou = __fdividef(inter, uni);
                int key = (__float_as_int(iou) & ~7) | (7 - n);
                best = max(best, key);
            }

            bool matched = __int_as_float(best & ~7) > 0.5f;

            // conf BCE via softplus (one exp + one log, both branches)
            float t = pb.x;
            float lg = __logf(1.0f + __expf(-fabsf(t)));
            float conf = (matched ? fmaxf(-t, 0.0f) : fmaxf(t, 0.0f)) + lg;
            local += fminf(conf, 100.0f);

            if (matched) {
                int bidx = 7 - (best & 7);
                float4 c = s_gtb[(tid << 3) | (bidx ^ sw)];
                int cls = __float_as_int(c.x) & 3;
                float gw = c.z - c.x, gh = c.w - c.y;
                float gx = (c.x + c.z) * 0.5f, gy = (c.y + c.w) * 0.5f;

                float dx = px - gx, dy = py - gy, dw = pw - gw, dh = ph - gh;
                float coord = dx * dx + dy * dy + dw * dw + dh * dh;

                float l0 = pb.y, l1 = pb.z, l2 = pb.w;
                float m = fmaxf(l0, fmaxf(l1, l2));
                float lse = m + __logf(__expf(l0 - m) + __expf(l1 - m) + __expf(l2 - m));
                float lc = (cls == 0) ? l0 : (cls == 1) ? l1 : l2;

                local += 5.0f * coord + (lse - lc);
            }
        }
    }

    // ---- block reduction: alias staging smem for scratch ----
    __syncthreads();                      // staging reads done; safe to alias
    float* s_red  = reinterpret_cast<float*>(s_p);
    double* s_d   = reinterpret_cast<double*>(s_p) + 8;

    float v = local;
#pragma unroll
    for (int o = 16; o > 0; o >>= 1) v += __shfl_down_sync(0xffffffffu, v, o);
    if (lane == 0) s_red[warp] = v;
    __syncthreads();
    if (warp == 0) {
        float w = (lane < TPB / 32) ? s_red[lane] : 0.0f;
#pragma unroll
        for (int o = 2; o > 0; o >>= 1) w += __shfl_down_sync(0xffffffffu, w, o);
        if (lane == 0) g_part[blockIdx.x] = w;
    }

    // ---- last-block-done final reduce ----
    __threadfence();
    if (tid == 0) {
        unsigned c = atomicAdd(&g_count, 1u);
        s_last = (c == (unsigned)(nblocks - 1));
    }
    __syncthreads();

    if (s_last) {
        float accf = 0.0f;
        for (int i = tid; i < nblocks; i += TPB) accf += g_part[i];
        double acc = (double)accf;
#pragma unroll
        for (int o = 16; o > 0; o >>= 1) acc += __shfl_down_sync(0xffffffffu, acc, o);
        if (lane == 0) s_d[warp] = acc;
        __syncthreads();
        if (warp == 0) {
            double w = (lane < TPB / 32) ? s_d[lane] : 0.0;
#pragma unroll
            for (int o = 2; o > 0; o >>= 1) w += __shfl_down_sync(0xffffffffu, w, o);
            if (lane == 0) {
                out[0] = (float)(w / (double)B);
                g_count = 0;
            }
        }
    }
}

extern "C" void kernel_launch(void* const* d_in, const int* in_sizes, int n_in,
                              void* d_out, int out_size) {
    const float4* pred = (const float4*)d_in[0];
    const float4* gtb  = (const float4*)d_in[1];
    const int*    gtc  = (const int*)d_in[2];
    float* out = (float*)d_out;

    int B = in_sizes[0] / 24;
    int nblocks = (B + BPB - 1) / BPB;

    if (B % BPB == 0)
        yolo_loss_kernel<true><<<nblocks, TPB>>>(pred, gtb, gtc, out, B, nblocks);
    else
        yolo_loss_kernel<false><<<nblocks, TPB>>>(pred, gtb, gtc, out, B, nblocks);
}

// round 7
// speedup vs baseline: 2.1229x; 1.0284x over previous
#include <cuda_runtime.h>

#define TPB 128
#define BPB 128
#define PERSIST_BLOCKS 592   // 4 blocks/SM * 148 SMs

__device__ float g_part[65536];
__device__ unsigned int g_count = 0;

__device__ __forceinline__ unsigned smem_u32(const void* p) {
    return (unsigned)__cvta_generic_to_shared(p);
}
__device__ __forceinline__ void cp16(unsigned dst, const void* src) {
    asm volatile("cp.async.cg.shared.global [%0], [%1], 16;" :: "r"(dst), "l"(src));
}
__device__ __forceinline__ void cp_commit() {
    asm volatile("cp.async.commit_group;" ::: "memory");
}
template <int N>
__device__ __forceinline__ void cp_wait() {
    asm volatile("cp.async.wait_group %0;" :: "n"(N) : "memory");
}

template <bool FULL>
__global__ __launch_bounds__(TPB, 4) void yolo_loss_kernel(
    const float4* __restrict__ pred,   // (B,3,8) f32 -> 6 float4 / batch
    const float4* __restrict__ gtb,    // (B,8,4) f32 -> 8 float4 / batch (raw center/wh)
    const int*   __restrict__ gtc,     // (B,8)   i32
    float* __restrict__ out,
    int B, int ntiles)
{
    // double-buffered: pa/pb split halves (stride 3 float4) + raw gtb (XOR swizzle)
    __shared__ float4 s_p  [2][BPB * 6];   // 2 x 12288 B
    __shared__ float4 s_gtb[2][BPB * 8];   // 2 x 16384 B   (total 57344 B)

    const int tid  = threadIdx.x;
    const int lane = tid & 31;
    const int warp = tid >> 5;
    const int sw   = tid & 7;
    const int gstep = gridDim.x;

    // ---- async stage of one tile into buffer `buf` ----
    auto stage = [&](int buf, int tile) {
        const char* psrc = (const char*)(pred + (size_t)tile * (BPB * 6));
        const char* gsrc = (const char*)(gtb  + (size_t)tile * (BPB * 8));
        // pred: 6 x 128 float4, scattered into split pa/pb layout
        int b = tid / 6, j = tid - (tid / 6) * 6;
#pragma unroll
        for (int it = 0; it < 6; it++) {
            int idx = it * TPB + tid;
            float4* dst = &s_p[buf][(j & 1) * (BPB * 3) + b * 3 + (j >> 1)];
            if (FULL || tile * BPB + b < B) cp16(smem_u32(dst), psrc + (size_t)idx * 16);
            else *dst = make_float4(0.f, 0.f, 0.f, 0.f);
            b += 21; j += 2;
            if (j >= 6) { j -= 6; b += 1; }
        }
        // gtb raw: 8 x 128 float4; n = tid&7 fixed, b = it*16 + tid>>3
        int n = tid & 7;
#pragma unroll
        for (int it = 0; it < 8; it++) {
            int bb = it * 16 + (tid >> 3);
            float4* dst = &s_gtb[buf][(bb << 3) | (n ^ (bb & 7))];
            if (FULL || tile * BPB + bb < B)
                cp16(smem_u32(dst), gsrc + (size_t)(it * TPB + tid) * 16);
            else *dst = make_float4(0.f, 0.f, 0.f, 0.f);
        }
    };

    // ---- pipelined persistent loop ----
    float local = 0.0f;
    int t = blockIdx.x;
    int cur = 0;

    if (t < ntiles) stage(0, t);
    cp_commit();

    while (t < ntiles) {
        int tn = t + gstep;
        if (tn < ntiles) stage(cur ^ 1, tn);
        cp_commit();                       // empty group OK on tail
        cp_wait<1>();                      // current buffer complete
        __syncthreads();

        if (FULL || t * BPB + tid < B) {
            const float4* myg = &s_gtb[cur][tid << 3];
            const float4* pA  = &s_p[cur][tid * 3];
            const float4* pB  = &s_p[cur][BPB * 3 + tid * 3];

#pragma unroll 1
            for (int a = 0; a < 3; a++) {
                float4 pa = pA[a];                 // x, y, w, h
                float4 pb = pB[a];                 // conf, l0, l1, l2

                float px = __fdividef(1.0f, 1.0f + __expf(-pa.x));
                float py = __fdividef(1.0f, 1.0f + __expf(-pa.y));
                float pw = pa.z, ph = pa.w;

                float px1 = px - pw * 0.5f, px2 = px + pw * 0.5f;
                float py1 = py - ph * 0.5f, py2 = py + ph * 0.5f;
                float pbase = (px2 - px1) * (py2 - py1) + 1e-6f;

                int best = (int)0x80000000;
#pragma unroll
                for (int n = 0; n < 8; n++) {
                    float4 g = myg[n ^ sw];        // cx, cy, w, h
                    float hw = g.z * 0.5f, hh = g.w * 0.5f;
                    float gx1 = g.x - hw, gx2 = g.x + hw;
                    float gy1 = g.y - hh, gy2 = g.y + hh;
                    float garea = (gx2 - gx1) * (gy2 - gy1);

                    float iw = fmaxf(fminf(px2, gx2) - fmaxf(px1, gx1), 0.0f);
                    float ih = fmaxf(fminf(py2, gy2) - fmaxf(py1, gy1), 0.0f);
                    float inter = iw * ih;
                    float uni = pbase + garea - inter;
                    float iou = __fdividef(inter, uni);
                    int key = (__float_as_int(iou) & ~7) | (7 - n);
                    best = max(best, key);
                }

                bool matched = __int_as_float(best & ~7) > 0.5f;

                float tc = pb.x;
                float lg = __logf(1.0f + __expf(-fabsf(tc)));
                float conf = (matched ? fmaxf(-tc, 0.0f) : fmaxf(tc, 0.0f)) + lg;
                local += fminf(conf, 100.0f);

                if (matched) {
                    int bidx = 7 - (best & 7);
                    float4 g = myg[bidx ^ sw];     // raw center/wh: exactly what we need
                    int cls = __ldg(gtc + ((size_t)(t * BPB + tid) << 3) + bidx);

                    float dx = px - g.x, dy = py - g.y;
                    float dw = pw - g.z, dh = ph - g.w;
                    float coord = dx * dx + dy * dy + dw * dw + dh * dh;

                    float l0 = pb.y, l1 = pb.z, l2 = pb.w;
                    float m = fmaxf(l0, fmaxf(l1, l2));
                    float lse = m + __logf(__expf(l0 - m) + __expf(l1 - m) + __expf(l2 - m));
                    float lc = (cls == 0) ? l0 : (cls == 1) ? l1 : l2;

                    local += 5.0f * coord + (lse - lc);
                }
            }
        }

        __syncthreads();                   // everyone done with buffer `cur`
        cur ^= 1;
        t = tn;
    }

    // ---- block reduction (alias smem; buffers are dead now) ----
    __syncthreads();
    float*  s_red  = reinterpret_cast<float*>(&s_gtb[0][0]);
    double* s_d    = reinterpret_cast<double*>(&s_gtb[0][8]);
    int*    s_flag = reinterpret_cast<int*>(&s_p[0][0]);

    float v = local;
#pragma unroll
    for (int o = 16; o > 0; o >>= 1) v += __shfl_down_sync(0xffffffffu, v, o);
    if (lane == 0) s_red[warp] = v;
    __syncthreads();
    if (warp == 0) {
        float w = (lane < TPB / 32) ? s_red[lane] : 0.0f;
#pragma unroll
        for (int o = 2; o > 0; o >>= 1) w += __shfl_down_sync(0xffffffffu, w, o);
        if (lane == 0) g_part[blockIdx.x] = w;
    }

    __threadfence();
    if (tid == 0) {
        unsigned c = atomicAdd(&g_count, 1u);
        *s_flag = (c == gridDim.x - 1);
    }
    __syncthreads();

    if (*s_flag) {
        float accf = 0.0f;
        for (int i = tid; i < (int)gridDim.x; i += TPB) accf += g_part[i];
        double acc = (double)accf;
#pragma unroll
        for (int o = 16; o > 0; o >>= 1) acc += __shfl_down_sync(0xffffffffu, acc, o);
        if (lane == 0) s_d[warp] = acc;
        __syncthreads();
        if (warp == 0) {
            double w = (lane < TPB / 32) ? s_d[lane] : 0.0;
#pragma unroll
            for (int o = 2; o > 0; o >>= 1) w += __shfl_down_sync(0xffffffffu, w, o);
            if (lane == 0) {
                out[0] = (float)(w / (double)B);
                g_count = 0;
            }
        }
    }
}

extern "C" void kernel_launch(void* const* d_in, const int* in_sizes, int n_in,
                              void* d_out, int out_size) {
    const float4* pred = (const float4*)d_in[0];
    const float4* gtb  = (const float4*)d_in[1];
    const int*    gtc  = (const int*)d_in[2];
    float* out = (float*)d_out;

    int B = in_sizes[0] / 24;
    int ntiles = (B + BPB - 1) / BPB;
    int grid = ntiles < PERSIST_BLOCKS ? ntiles : PERSIST_BLOCKS;

    if (B % BPB == 0)
        yolo_loss_kernel<true><<<grid, TPB>>>(pred, gtb, gtc, out, B, ntiles);
    else
        yolo_loss_kernel<false><<<grid, TPB>>>(pred, gtb, gtc, out, B, ntiles);
}